// round 14
// baseline (speedup 1.0000x reference)
#include <cuda_runtime.h>
#include <cstdint>

// 2D DCT-II (4096x4096) as two NT GEMMs on int8 IMMA tensor cores.
//   T = gemm_nt(D, X);  Y = gemm_nt(D, T);   C[i][j] = sum_k A[i][k]*B[j][k]
// fp32 emulated via two-level int8 fixed point:
//   a ~= s*(q1 + q2/254),  C = sA*sB*(S1 + S2/254)
//   S1 = q1*r1 (IMMA),  S2 = q1*r2 + q2*r1 (two IMMAs, shared s32 accum)
// m16n8k32.s8 fragments are byte-identical to m16n8k16.bf16 -> same
// smem/ldmatrix machinery, half the iterations, half the MMA instructions.

constexpr int MN = 4096;
constexpr int BM = 128, BN = 128, BK = 64;  // BK in int8 elements (64 B rows)
constexpr int NC = MN / BK;                 // 64 k-iterations
constexpr int STAGES = 4;

constexpr uint32_t ROWB = 80;                   // 64B data + 16B pad
constexpr uint32_t TILE_B = 128 * ROWB;         // 10240 B per operand tile
constexpr uint32_t OFF_A1 = 0;
constexpr uint32_t OFF_A2 = TILE_B;
constexpr uint32_t OFF_B1 = 2 * TILE_B;
constexpr uint32_t OFF_B2 = 3 * TILE_B;
constexpr uint32_t STAGE_B = 4 * TILE_B;        // 40960 B
constexpr uint32_t SMEM_SZ = STAGES * STAGE_B;  // 163840 B

// int8 quantized operands (bit patterns in unsigned char)
__device__ __align__(256) unsigned char g_Dq1[(size_t)MN * MN];
__device__ __align__(256) unsigned char g_Dq2[(size_t)MN * MN];
__device__ __align__(256) unsigned char g_Xq1[(size_t)MN * MN];
__device__ __align__(256) unsigned char g_Xq2[(size_t)MN * MN];
__device__ __align__(256) unsigned char g_Tq1[(size_t)MN * MN];
__device__ __align__(256) unsigned char g_Tq2[(size_t)MN * MN];
__device__ __align__(256) float g_T[(size_t)MN * MN];  // fp32 intermediate
__device__ float g_maxX;
__device__ float g_maxT;

// ---------------- PTX helpers ----------------
__device__ __forceinline__ uint32_t smem_u32(const void* p) {
    uint32_t a;
    asm("{ .reg .u64 t; cvta.to.shared.u64 t, %1; cvt.u32.u64 %0, t; }" : "=r"(a) : "l"(p));
    return a;
}
__device__ __forceinline__ void cp16(uint32_t dst, const void* src) {
    asm volatile("cp.async.cg.shared.global [%0], [%1], 16;" ::"r"(dst), "l"(src) : "memory");
}
__device__ __forceinline__ void cp_commit() { asm volatile("cp.async.commit_group;" ::: "memory"); }
__device__ __forceinline__ void cp_wait2() { asm volatile("cp.async.wait_group 2;" ::: "memory"); }

__device__ __forceinline__ void ldsm4(uint32_t* r, uint32_t addr) {
    asm volatile("ldmatrix.sync.aligned.m8n8.x4.shared.b16 {%0,%1,%2,%3}, [%4];"
                 : "=r"(r[0]), "=r"(r[1]), "=r"(r[2]), "=r"(r[3])
                 : "r"(addr));
}
__device__ __forceinline__ void imma(int* c, const uint32_t* a, uint32_t b0, uint32_t b1) {
    asm volatile(
        "mma.sync.aligned.m16n8k32.row.col.s32.s8.s8.s32 "
        "{%0,%1,%2,%3}, {%4,%5,%6,%7}, {%8,%9}, {%0,%1,%2,%3};"
        : "+r"(c[0]), "+r"(c[1]), "+r"(c[2]), "+r"(c[3])
        : "r"(a[0]), "r"(a[1]), "r"(a[2]), "r"(a[3]), "r"(b0), "r"(b1));
}

// ---------------- quantization ----------------
// aq = a/s (|aq| <= 127);  q1 = rint(aq);  q2 = rint((aq - q1)*254)
__device__ __forceinline__ void quant2(float aq, signed char& c1, signed char& c2) {
    float q1 = rintf(aq);
    c1 = (signed char)(int)q1;
    c2 = (signed char)(int)rintf((aq - q1) * 254.0f);
}

__global__ void init_max_kernel() {
    g_maxX = 0.0f;
    g_maxT = 0.0f;
}

// which=0: src = x (arg), dst g_maxX;  which=1: src = g_T, dst g_maxT
__global__ void reduce_max_kernel(const float* __restrict__ xsrc, int which) {
    const float4* p = (const float4*)(which ? (const float*)g_T : xsrc);
    float m = 0.0f;
    for (unsigned i = blockIdx.x * blockDim.x + threadIdx.x; i < (MN * MN / 4);
         i += gridDim.x * blockDim.x) {
        float4 v = p[i];
        m = fmaxf(m, fmaxf(fmaxf(fabsf(v.x), fabsf(v.y)), fmaxf(fabsf(v.z), fabsf(v.w))));
    }
#pragma unroll
    for (int o = 16; o > 0; o >>= 1) m = fmaxf(m, __shfl_xor_sync(0xFFFFFFFFu, m, o));
    if ((threadIdx.x & 31) == 0) {
        int* dst = (int*)(which ? &g_maxT : &g_maxX);
        atomicMax(dst, __float_as_int(m));  // valid: all values >= 0
    }
}

__global__ void fill_dct_quant_kernel() {
    unsigned idx = blockIdx.x * blockDim.x + threadIdx.x;
    unsigned i4 = idx * 4;
    unsigned k = i4 >> 12;
    unsigned m0 = i4 & (MN - 1);
    signed char q1[4], q2[4];
#pragma unroll
    for (int j = 0; j < 4; j++) {
        unsigned m = m0 + j;
        unsigned t = (k * (2u * m + 1u)) & (4u * MN - 1u);
        float c = cospif((float)t * (1.0f / (2.0f * (float)MN)));
        quant2(c * 127.0f, q1[j], q2[j]);  // sD = 1/127
    }
    ((uchar4*)g_Dq1)[idx] = make_uchar4(q1[0], q1[1], q1[2], q1[3]);
    ((uchar4*)g_Dq2)[idx] = make_uchar4(q2[0], q2[1], q2[2], q2[3]);
}

// which=0: src = x (arg), scale g_maxX, dst g_Xq*;  which=1: src = g_T, scale g_maxT, dst g_Tq*
__global__ void quant_kernel(const float* __restrict__ xsrc, int which) {
    unsigned idx = blockIdx.x * blockDim.x + threadIdx.x;
    const float inv_s = 127.0f / (which ? g_maxT : g_maxX);
    const float4* src = (const float4*)(which ? (const float*)g_T : xsrc);
    unsigned char* d1 = which ? g_Tq1 : g_Xq1;
    unsigned char* d2 = which ? g_Tq2 : g_Xq2;
    float4 v = src[idx];
    signed char q1[4], q2[4];
    quant2(v.x * inv_s, q1[0], q2[0]);
    quant2(v.y * inv_s, q1[1], q2[1]);
    quant2(v.z * inv_s, q1[2], q2[2]);
    quant2(v.w * inv_s, q1[3], q2[3]);
    ((uchar4*)d1)[idx] = make_uchar4(q1[0], q1[1], q1[2], q1[3]);
    ((uchar4*)d2)[idx] = make_uchar4(q2[0], q2[1], q2[2], q2[3]);
}

// ---------------- GEMM ----------------
// MODE 0: B = Xq, C -> g_T (fp32), scale sD*sX
// MODE 1: B = Tq, C -> out (fp32), scale sD*sT
template <int MODE>
__global__ void __launch_bounds__(256, 1) dct_gemm_kernel(float* __restrict__ outp) {
    extern __shared__ __align__(128) char smem[];
    const uint32_t sbase = smem_u32(smem);
    const int tid = threadIdx.x;
    const int lane = tid & 31;
    const int wid = tid >> 5;
    const int wm = wid & 1;   // 2 warps along M (64 rows each)
    const int wn = wid >> 1;  // 4 warps along N (32 cols each)
    const int ntile = blockIdx.x;
    const int mtile = blockIdx.y;

    const unsigned char* __restrict__ A1 = g_Dq1;
    const unsigned char* __restrict__ A2 = g_Dq2;
    const unsigned char* __restrict__ B1 = (MODE == 0) ? g_Xq1 : g_Tq1;
    const unsigned char* __restrict__ B2 = (MODE == 0) ? g_Xq2 : g_Tq2;
    float* __restrict__ C = (MODE == 0) ? g_T : outp;

    // ---- loader geometry: each thread moves 2 x 16B per operand tile ----
    const int row0 = tid >> 2;  // 0..63
    const int c0 = tid & 3;     // 16B chunk within 64B row
    const uint32_t d0 = (uint32_t)row0 * ROWB + (uint32_t)c0 * 16;
    const uint32_t d1 = d0 + 64 * ROWB;
    const size_t aoff = (size_t)(mtile * BM + row0) * MN + c0 * 16;
    const size_t boff = (size_t)(ntile * BN + row0) * MN + c0 * 16;
    const size_t rstep = (size_t)64 * MN;

    auto load_iter = [&](int it, int s) {
        const uint32_t sb = sbase + (uint32_t)s * STAGE_B;
        const size_t ko = (size_t)it * BK;
        cp16(sb + OFF_A1 + d0, A1 + aoff + ko);
        cp16(sb + OFF_A1 + d1, A1 + aoff + rstep + ko);
        cp16(sb + OFF_A2 + d0, A2 + aoff + ko);
        cp16(sb + OFF_A2 + d1, A2 + aoff + rstep + ko);
        cp16(sb + OFF_B1 + d0, B1 + boff + ko);
        cp16(sb + OFF_B1 + d1, B1 + boff + rstep + ko);
        cp16(sb + OFF_B2 + d0, B2 + boff + ko);
        cp16(sb + OFF_B2 + d1, B2 + boff + rstep + ko);
    };

    // ---- ldmatrix per-lane address offsets (byte-identical to bf16 k16) ----
    const int mt = lane >> 3;
    const uint32_t a_off = (uint32_t)(wm * 64 + (mt & 1) * 8 + (lane & 7)) * ROWB +
                           (uint32_t)((mt >> 1) * 16);
    const uint32_t b_off = (uint32_t)(wn * 32 + (mt >> 1) * 8 + (lane & 7)) * ROWB +
                           (uint32_t)((mt & 1) * 16);

    int accA[4][4][4], accB[4][4][4];
#pragma unroll
    for (int i = 0; i < 4; i++)
#pragma unroll
        for (int j = 0; j < 4; j++)
#pragma unroll
            for (int q = 0; q < 4; q++) {
                accA[i][j][q] = 0;
                accB[i][j][q] = 0;
            }

    // prologue: stages 0,1,2 in flight
    load_iter(0, 0);
    cp_commit();
    load_iter(1, 1);
    cp_commit();
    load_iter(2, 2);
    cp_commit();

    for (int it = 0; it < NC; ++it) {
        cp_wait2();
        __syncthreads();

        if (it + 3 < NC) load_iter(it + 3, (it + 3) % STAGES);
        cp_commit();

        const uint32_t sb = sbase + (uint32_t)(it % STAGES) * STAGE_B;
#pragma unroll
        for (int ks = 0; ks < 2; ks++) {
            const uint32_t ck = (uint32_t)ks * 32;  // k32 step = 32 bytes
            uint32_t aq1[4][4], aq2[4][4];
#pragma unroll
            for (int mi = 0; mi < 4; mi++) {
                ldsm4(aq1[mi], sb + OFF_A1 + a_off + (uint32_t)mi * (16 * ROWB) + ck);
                ldsm4(aq2[mi], sb + OFF_A2 + a_off + (uint32_t)mi * (16 * ROWB) + ck);
            }
            uint32_t bq1[2][4], bq2[2][4];
#pragma unroll
            for (int bp = 0; bp < 2; bp++) {
                ldsm4(bq1[bp], sb + OFF_B1 + b_off + (uint32_t)bp * (16 * ROWB) + ck);
                ldsm4(bq2[bp], sb + OFF_B2 + b_off + (uint32_t)bp * (16 * ROWB) + ck);
            }
#pragma unroll
            for (int mi = 0; mi < 4; mi++)
#pragma unroll
                for (int ni = 0; ni < 4; ni++) {
                    const int bp = ni >> 1, pr = (ni & 1) * 2;
                    imma(accA[mi][ni], aq1[mi], bq1[bp][pr], bq1[bp][pr + 1]);
                    imma(accB[mi][ni], aq1[mi], bq2[bp][pr], bq2[bp][pr + 1]);
                    imma(accB[mi][ni], aq2[mi], bq1[bp][pr], bq1[bp][pr + 1]);
                }
        }
    }

    // ---- epilogue: C = sA*sB*(S1 + S2/254) ----
    const float sB = (MODE == 0 ? g_maxX : g_maxT) * (1.0f / 127.0f);
    const float scale = (1.0f / 127.0f) * sB;
    const int g = lane >> 2;
    const int cpair = (lane & 3) * 2;
#pragma unroll
    for (int mi = 0; mi < 4; mi++) {
#pragma unroll
        for (int ni = 0; ni < 4; ni++) {
            const int r0 = mtile * BM + wm * 64 + mi * 16 + g;
            const int r1 = r0 + 8;
            const int col = ntile * BN + wn * 32 + ni * 8 + cpair;
            float f0 = scale * ((float)accA[mi][ni][0] + (float)accB[mi][ni][0] * (1.0f / 254.0f));
            float f1 = scale * ((float)accA[mi][ni][1] + (float)accB[mi][ni][1] * (1.0f / 254.0f));
            float f2 = scale * ((float)accA[mi][ni][2] + (float)accB[mi][ni][2] * (1.0f / 254.0f));
            float f3 = scale * ((float)accA[mi][ni][3] + (float)accB[mi][ni][3] * (1.0f / 254.0f));
            *(float2*)(C + (size_t)r0 * MN + col) = make_float2(f0, f1);
            *(float2*)(C + (size_t)r1 * MN + col) = make_float2(f2, f3);
        }
    }
}

extern "C" void kernel_launch(void* const* d_in, const int* in_sizes, int n_in, void* d_out,
                              int out_size) {
    const float* x = (const float*)d_in[0];
    float* out = (float*)d_out;

    cudaFuncSetAttribute(dct_gemm_kernel<0>, cudaFuncAttributeMaxDynamicSharedMemorySize, SMEM_SZ);
    cudaFuncSetAttribute(dct_gemm_kernel<1>, cudaFuncAttributeMaxDynamicSharedMemorySize, SMEM_SZ);

    init_max_kernel<<<1, 1>>>();
    fill_dct_quant_kernel<<<(MN * MN / 4) / 256, 256>>>();
    reduce_max_kernel<<<2048, 256>>>(x, 0);
    quant_kernel<<<(MN * MN / 4) / 256, 256>>>(x, 0);

    dim3 grid(MN / BN, MN / BM);  // (32, 32)
    dct_gemm_kernel<0><<<grid, 256, SMEM_SZ>>>(nullptr);  // -> g_T

    reduce_max_kernel<<<2048, 256>>>(nullptr, 1);          // max|T| -> g_maxT
    quant_kernel<<<(MN * MN / 4) / 256, 256>>>(nullptr, 1);  // T -> g_Tq1/g_Tq2

    dct_gemm_kernel<1><<<grid, 256, SMEM_SZ>>>(out);
}

// round 15
// speedup vs baseline: 4.1818x; 4.1818x over previous
#include <cuda_runtime.h>
#include <cuda_bf16.h>
#include <cstdint>

// 2D DCT-II (4096x4096), cosine-symmetry folded: D[k][N-1-m]=(-1)^k D[k][m]
//   => C[k] = sum_{m<N/2} (x[m] + (-1)^k x[N-1-m]) * D[k][m]
// Each pass = 2 half-size NT GEMMs (even-k: De x X+, odd-k: Do x X-),
// K=2048, M=2048, Ncols=4096  ->  1/2 the MACs of the unfolded pass.
// GEMM engine = R12 best (HMMA bf16-split, 4-stage cp.async, frag dbuf).

constexpr int MNF = 4096;  // full size
constexpr int MNH = 2048;  // folded size
constexpr int BM = 128, BN = 128, BK = 32;
constexpr int NC = MNH / BK;  // 64 k-iterations
constexpr int STAGES = 4;

constexpr uint32_t ROWB = 80;                   // 64B data + 16B pad
constexpr uint32_t TILE_B = 128 * ROWB;         // 10240
constexpr uint32_t OFF_AH = 0;
constexpr uint32_t OFF_AL = TILE_B;
constexpr uint32_t OFF_BH = 2 * TILE_B;
constexpr uint32_t OFF_BL = 3 * TILE_B;
constexpr uint32_t STAGE_B = 4 * TILE_B;        // 40960
constexpr uint32_t SMEM_SZ = STAGES * STAGE_B;  // 163840

// bf16 bit-pattern scratch
__device__ __align__(256) unsigned short g_Dehi[(size_t)MNH * MNH];
__device__ __align__(256) unsigned short g_Delo[(size_t)MNH * MNH];
__device__ __align__(256) unsigned short g_Dohi[(size_t)MNH * MNH];
__device__ __align__(256) unsigned short g_Dolo[(size_t)MNH * MNH];
__device__ __align__(256) unsigned short g_Xphi[(size_t)MNF * MNH];
__device__ __align__(256) unsigned short g_Xplo[(size_t)MNF * MNH];
__device__ __align__(256) unsigned short g_Xmhi[(size_t)MNF * MNH];
__device__ __align__(256) unsigned short g_Xmlo[(size_t)MNF * MNH];
__device__ __align__(256) unsigned short g_Tphi[(size_t)MNF * MNH];
__device__ __align__(256) unsigned short g_Tplo[(size_t)MNF * MNH];
__device__ __align__(256) unsigned short g_Tmhi[(size_t)MNF * MNH];
__device__ __align__(256) unsigned short g_Tmlo[(size_t)MNF * MNH];
__device__ __align__(256) float g_T[(size_t)MNF * MNF];  // fp32 intermediate

// ---------------- PTX helpers ----------------
__device__ __forceinline__ uint32_t smem_u32(const void* p) {
    uint32_t a;
    asm("{ .reg .u64 t; cvta.to.shared.u64 t, %1; cvt.u32.u64 %0, t; }" : "=r"(a) : "l"(p));
    return a;
}
__device__ __forceinline__ void cp16(uint32_t dst, const void* src) {
    asm volatile("cp.async.cg.shared.global [%0], [%1], 16;" ::"r"(dst), "l"(src) : "memory");
}
__device__ __forceinline__ void cp_commit() { asm volatile("cp.async.commit_group;" ::: "memory"); }
__device__ __forceinline__ void cp_wait2() { asm volatile("cp.async.wait_group 2;" ::: "memory"); }

__device__ __forceinline__ void ldsm4(uint32_t* r, uint32_t addr) {
    asm volatile("ldmatrix.sync.aligned.m8n8.x4.shared.b16 {%0,%1,%2,%3}, [%4];"
                 : "=r"(r[0]), "=r"(r[1]), "=r"(r[2]), "=r"(r[3])
                 : "r"(addr));
}
__device__ __forceinline__ void mma_bf16(float* c, const uint32_t* a, uint32_t b0, uint32_t b1) {
    asm volatile(
        "mma.sync.aligned.m16n8k16.row.col.f32.bf16.bf16.f32 "
        "{%0,%1,%2,%3}, {%4,%5,%6,%7}, {%8,%9}, {%0,%1,%2,%3};"
        : "+f"(c[0]), "+f"(c[1]), "+f"(c[2]), "+f"(c[3])
        : "r"(a[0]), "r"(a[1]), "r"(a[2]), "r"(a[3]), "r"(b0), "r"(b1));
}

// ---------------- split / fill / fold ----------------
__device__ __forceinline__ void split_bf16(float v, unsigned short& h, unsigned short& l) {
    __nv_bfloat16 bh = __float2bfloat16_rn(v);
    float fh = __bfloat162float(bh);
    __nv_bfloat16 bl = __float2bfloat16_rn(v - fh);
    h = __bfloat16_as_ushort(bh);
    l = __bfloat16_as_ushort(bl);
}

// De[j][m] = cos(pi*(2j)(2m+1)/8192), Do[j][m] = cos(pi*(2j+1)(2m+1)/8192)
__global__ void fill_basis_kernel() {
    unsigned idx = blockIdx.x * blockDim.x + threadIdx.x;
    unsigned i4 = idx * 4;
    unsigned j = i4 >> 11;          // 0..2047
    unsigned m0 = i4 & (MNH - 1);   // 0..2047
    unsigned short eh[4], el[4], oh[4], ol[4];
#pragma unroll
    for (int q = 0; q < 4; q++) {
        unsigned m2 = 2u * (m0 + q) + 1u;
        unsigned ue = (2u * j * m2) & 16383u;
        unsigned uo = ((2u * j + 1u) * m2) & 16383u;
        split_bf16(cospif((float)ue * (1.0f / 8192.0f)), eh[q], el[q]);
        split_bf16(cospif((float)uo * (1.0f / 8192.0f)), oh[q], ol[q]);
    }
    ((uint2*)g_Dehi)[idx] = make_uint2((uint32_t)eh[0] | ((uint32_t)eh[1] << 16),
                                       (uint32_t)eh[2] | ((uint32_t)eh[3] << 16));
    ((uint2*)g_Delo)[idx] = make_uint2((uint32_t)el[0] | ((uint32_t)el[1] << 16),
                                       (uint32_t)el[2] | ((uint32_t)el[3] << 16));
    ((uint2*)g_Dohi)[idx] = make_uint2((uint32_t)oh[0] | ((uint32_t)oh[1] << 16),
                                       (uint32_t)oh[2] | ((uint32_t)oh[3] << 16));
    ((uint2*)g_Dolo)[idx] = make_uint2((uint32_t)ol[0] | ((uint32_t)ol[1] << 16),
                                       (uint32_t)ol[2] | ((uint32_t)ol[3] << 16));
}

// fold rows of a 4096x4096 fp32 matrix: p[m]=s[m]+s[4095-m], d[m]=s[m]-s[4095-m]
// which=0: src = xsrc (input), dst g_Xp*/g_Xm*;  which=1: src = g_T, dst g_Tp*/g_Tm*
__global__ void fold_split_kernel(const float* __restrict__ xsrc, int which) {
    unsigned idx = blockIdx.x * blockDim.x + threadIdx.x;  // over MNF*MNH/4
    unsigned row = idx >> 9;            // MNH/4 = 512 float4 per row
    unsigned m0 = (idx & 511u) * 4u;
    const float* src = which ? (const float*)g_T : xsrc;
    unsigned short* ph = which ? g_Tphi : g_Xphi;
    unsigned short* pl = which ? g_Tplo : g_Xplo;
    unsigned short* mh = which ? g_Tmhi : g_Xmhi;
    unsigned short* ml = which ? g_Tmlo : g_Xmlo;

    float4 f = *(const float4*)(src + (size_t)row * MNF + m0);
    float4 r = *(const float4*)(src + (size_t)row * MNF + (MNF - 4 - m0));
    float fv[4] = {f.x, f.y, f.z, f.w};
    float rv[4] = {r.w, r.z, r.y, r.x};  // reversed
    unsigned short hp[4], lp[4], hm[4], lm[4];
#pragma unroll
    for (int q = 0; q < 4; q++) {
        split_bf16(fv[q] + rv[q], hp[q], lp[q]);
        split_bf16(fv[q] - rv[q], hm[q], lm[q]);
    }
    size_t o = (size_t)row * MNH + m0;
    *(uint2*)(ph + o) = make_uint2((uint32_t)hp[0] | ((uint32_t)hp[1] << 16),
                                   (uint32_t)hp[2] | ((uint32_t)hp[3] << 16));
    *(uint2*)(pl + o) = make_uint2((uint32_t)lp[0] | ((uint32_t)lp[1] << 16),
                                   (uint32_t)lp[2] | ((uint32_t)lp[3] << 16));
    *(uint2*)(mh + o) = make_uint2((uint32_t)hm[0] | ((uint32_t)hm[1] << 16),
                                   (uint32_t)hm[2] | ((uint32_t)hm[3] << 16));
    *(uint2*)(ml + o) = make_uint2((uint32_t)lm[0] | ((uint32_t)lm[1] << 16),
                                   (uint32_t)lm[2] | ((uint32_t)lm[3] << 16));
}

// ---------------- GEMM ----------------
// C[j][i] = sum_m A[j][m]*B[i][m];  A: 2048x2048 (De or Do), B: 4096x2048.
// Output row j is scattered to dst row (2*j + PAR), dst is 4096-wide fp32.
// PASS 0: B = Xp/Xm, dst = g_T;  PASS 1: B = Tp/Tm, dst = outp.
template <int PASS, int PAR>
__global__ void __launch_bounds__(256, 1) dct_gemm_kernel(float* __restrict__ outp) {
    extern __shared__ __align__(128) char smem[];
    const uint32_t sbase = smem_u32(smem);
    const int tid = threadIdx.x;
    const int lane = tid & 31;
    const int wid = tid >> 5;
    const int wm = wid & 1;   // 2 warps along M (64 rows each)
    const int wn = wid >> 1;  // 4 warps along N (32 cols each)
    const int ntile = blockIdx.x;  // 0..31  (B rows / output cols)
    const int mtile = blockIdx.y;  // 0..15  (A rows / output rows)

    const unsigned short* __restrict__ Ah = PAR ? g_Dohi : g_Dehi;
    const unsigned short* __restrict__ Al = PAR ? g_Dolo : g_Delo;
    const unsigned short* __restrict__ Bh =
        (PASS == 0) ? (PAR ? g_Xmhi : g_Xphi) : (PAR ? g_Tmhi : g_Tphi);
    const unsigned short* __restrict__ Bl =
        (PASS == 0) ? (PAR ? g_Xmlo : g_Xplo) : (PAR ? g_Tmlo : g_Tplo);
    float* __restrict__ C = (PASS == 0) ? g_T : outp;

    // ---- loader geometry: each thread moves 2 x 16B per operand tile ----
    const int row0 = tid >> 2;  // 0..63
    const int c0 = tid & 3;
    const uint32_t d0 = (uint32_t)row0 * ROWB + (uint32_t)c0 * 16;
    const uint32_t d1 = d0 + 64 * ROWB;
    const size_t aoff = (size_t)(mtile * BM + row0) * MNH + c0 * 8;
    const size_t boff = (size_t)(ntile * BN + row0) * MNH + c0 * 8;
    const size_t rstep = (size_t)64 * MNH;

    auto load_iter = [&](int it, int s) {
        const uint32_t sb = sbase + (uint32_t)s * STAGE_B;
        const size_t ko = (size_t)it * BK;
        cp16(sb + OFF_AH + d0, Ah + aoff + ko);
        cp16(sb + OFF_AH + d1, Ah + aoff + rstep + ko);
        cp16(sb + OFF_AL + d0, Al + aoff + ko);
        cp16(sb + OFF_AL + d1, Al + aoff + rstep + ko);
        cp16(sb + OFF_BH + d0, Bh + boff + ko);
        cp16(sb + OFF_BH + d1, Bh + boff + rstep + ko);
        cp16(sb + OFF_BL + d0, Bl + boff + ko);
        cp16(sb + OFF_BL + d1, Bl + boff + rstep + ko);
    };

    // ---- ldmatrix per-lane address offsets ----
    const int mt = lane >> 3;
    const uint32_t a_off = (uint32_t)(wm * 64 + (mt & 1) * 8 + (lane & 7)) * ROWB +
                           (uint32_t)((mt >> 1) * 16);
    const uint32_t b_off = (uint32_t)(wn * 32 + (mt >> 1) * 8 + (lane & 7)) * ROWB +
                           (uint32_t)((mt & 1) * 16);

    float acc[4][4][4];
#pragma unroll
    for (int i = 0; i < 4; i++)
#pragma unroll
        for (int j = 0; j < 4; j++)
#pragma unroll
            for (int q = 0; q < 4; q++) acc[i][j][q] = 0.0f;

    uint32_t ah[2][4][4], al[2][4][4], bh[2][2][4], bl[2][2][4];

    auto load_frags = [&](uint32_t sb, int buf, int ks) {
        const uint32_t ck = (uint32_t)ks * 32;
#pragma unroll
        for (int mi = 0; mi < 4; mi++) {
            ldsm4(ah[buf][mi], sb + OFF_AH + a_off + (uint32_t)mi * (16 * ROWB) + ck);
            ldsm4(al[buf][mi], sb + OFF_AL + a_off + (uint32_t)mi * (16 * ROWB) + ck);
        }
#pragma unroll
        for (int bp = 0; bp < 2; bp++) {
            ldsm4(bh[buf][bp], sb + OFF_BH + b_off + (uint32_t)bp * (16 * ROWB) + ck);
            ldsm4(bl[buf][bp], sb + OFF_BL + b_off + (uint32_t)bp * (16 * ROWB) + ck);
        }
    };
    auto mma_frags = [&](int buf) {
#pragma unroll
        for (int mi = 0; mi < 4; mi++)
#pragma unroll
            for (int ni = 0; ni < 4; ni++) {
                const int bp = ni >> 1, pr = (ni & 1) * 2;
                mma_bf16(acc[mi][ni], ah[buf][mi], bh[buf][bp][pr], bh[buf][bp][pr + 1]);
                mma_bf16(acc[mi][ni], ah[buf][mi], bl[buf][bp][pr], bl[buf][bp][pr + 1]);
                mma_bf16(acc[mi][ni], al[buf][mi], bh[buf][bp][pr], bh[buf][bp][pr + 1]);
            }
    };

    load_iter(0, 0);
    cp_commit();
    load_iter(1, 1);
    cp_commit();
    load_iter(2, 2);
    cp_commit();

    for (int it = 0; it < NC; ++it) {
        cp_wait2();
        __syncthreads();

        if (it + 3 < NC) load_iter(it + 3, (it + 3) % STAGES);
        cp_commit();

        const uint32_t sb = sbase + (uint32_t)(it % STAGES) * STAGE_B;
        load_frags(sb, 0, 0);
        load_frags(sb, 1, 1);
        mma_frags(0);
        mma_frags(1);
    }

    // ---- epilogue: fp32, rows interleaved by parity ----
    const int g = lane >> 2;
    const int cpair = (lane & 3) * 2;
#pragma unroll
    for (int mi = 0; mi < 4; mi++) {
#pragma unroll
        for (int ni = 0; ni < 4; ni++) {
            const int j0 = mtile * BM + wm * 64 + mi * 16 + g;   // A-row (freq/2)
            const int j1 = j0 + 8;
            const int col = ntile * BN + wn * 32 + ni * 8 + cpair;  // B-row (output col)
            *(float2*)(C + (size_t)(2 * j0 + PAR) * MNF + col) =
                make_float2(acc[mi][ni][0], acc[mi][ni][1]);
            *(float2*)(C + (size_t)(2 * j1 + PAR) * MNF + col) =
                make_float2(acc[mi][ni][2], acc[mi][ni][3]);
        }
    }
}

extern "C" void kernel_launch(void* const* d_in, const int* in_sizes, int n_in, void* d_out,
                              int out_size) {
    const float* x = (const float*)d_in[0];
    float* out = (float*)d_out;

    cudaFuncSetAttribute(dct_gemm_kernel<0, 0>, cudaFuncAttributeMaxDynamicSharedMemorySize, SMEM_SZ);
    cudaFuncSetAttribute(dct_gemm_kernel<0, 1>, cudaFuncAttributeMaxDynamicSharedMemorySize, SMEM_SZ);
    cudaFuncSetAttribute(dct_gemm_kernel<1, 0>, cudaFuncAttributeMaxDynamicSharedMemorySize, SMEM_SZ);
    cudaFuncSetAttribute(dct_gemm_kernel<1, 1>, cudaFuncAttributeMaxDynamicSharedMemorySize, SMEM_SZ);

    fill_basis_kernel<<<(MNH * MNH / 4) / 256, 256>>>();
    fold_split_kernel<<<(MNF * MNH / 4) / 256, 256>>>(x, 0);

    dim3 grid(MNF / BN, MNH / BM);  // (32, 16)
    dct_gemm_kernel<0, 0><<<grid, 256, SMEM_SZ>>>(nullptr);  // even k -> g_T
    dct_gemm_kernel<0, 1><<<grid, 256, SMEM_SZ>>>(nullptr);  // odd  k -> g_T

    fold_split_kernel<<<(MNF * MNH / 4) / 256, 256>>>(nullptr, 1);  // fold T

    dct_gemm_kernel<1, 0><<<grid, 256, SMEM_SZ>>>(out);  // even k -> out
    dct_gemm_kernel<1, 1><<<grid, 256, SMEM_SZ>>>(out);  // odd  k -> out
}

// round 17
// speedup vs baseline: 6.5451x; 1.5652x over previous
#include <cuda_runtime.h>
#include <cuda_bf16.h>
#include <cstdint>

// 2D DCT-II (4096x4096), two-level cosine-symmetry fold per pass:
//   level 1: C[2j]   = sum_{m<2048} p[m]   De[j][m],  p = x[m]+x[4095-m]
//            C[2j+1] = sum_{m<2048} d[m]   Do[j][m],  d = x[m]-x[4095-m]
//   level 2 (even branch only; De[j][2047-m] = (-1)^j De[j][m]):
//            C[4j']   = sum_{m<1024} pp[m] Dee[j'][m], pp = p[m]+p[2047-m]
//            C[4j'+2] = sum_{m<1024} pm[m] Deo[j'][m], pm = p[m]-p[2047-m]
//   => MACs = 0.75 * (level-1 only) = 0.375 * unfolded.
// All three GEMMs of a pass run in ONE 1024-CTA launch (blockIdx.y dispatch,
// heavy odd-branch CTAs first) to kill wave-tail quantization.
// GEMM engine = R12 (HMMA bf16-split, 4-stage cp.async, frag double-buffer).

constexpr int MNF = 4096;  // full size
constexpr int MNH = 2048;  // level-1 folded
constexpr int MNQ = 1024;  // level-2 folded
constexpr int BM = 128, BN = 128, BK = 32;
constexpr int STAGES = 4;

constexpr uint32_t ROWB = 80;                   // 64B data + 16B pad
constexpr uint32_t TILE_B = 128 * ROWB;         // 10240
constexpr uint32_t OFF_AH = 0;
constexpr uint32_t OFF_AL = TILE_B;
constexpr uint32_t OFF_BH = 2 * TILE_B;
constexpr uint32_t OFF_BL = 3 * TILE_B;
constexpr uint32_t STAGE_B = 4 * TILE_B;        // 40960
constexpr uint32_t SMEM_SZ = STAGES * STAGE_B;  // 163840

// bf16 bit-pattern scratch. B-side buffers are reused for both passes.
__device__ __align__(256) unsigned short g_Dohi[(size_t)MNH * MNH];
__device__ __align__(256) unsigned short g_Dolo[(size_t)MNH * MNH];
__device__ __align__(256) unsigned short g_Deehi[(size_t)MNQ * MNQ];
__device__ __align__(256) unsigned short g_Deelo[(size_t)MNQ * MNQ];
__device__ __align__(256) unsigned short g_Deohi[(size_t)MNQ * MNQ];
__device__ __align__(256) unsigned short g_Deolo[(size_t)MNQ * MNQ];
__device__ __align__(256) unsigned short g_Bmhi[(size_t)MNF * MNH];   // d (level-1 odd)
__device__ __align__(256) unsigned short g_Bmlo[(size_t)MNF * MNH];
__device__ __align__(256) unsigned short g_Bpphi[(size_t)MNF * MNQ];  // pp
__device__ __align__(256) unsigned short g_Bpplo[(size_t)MNF * MNQ];
__device__ __align__(256) unsigned short g_Bpmhi[(size_t)MNF * MNQ];  // pm
__device__ __align__(256) unsigned short g_Bpmlo[(size_t)MNF * MNQ];
__device__ __align__(256) float g_T[(size_t)MNF * MNF];  // fp32 intermediate

// ---------------- PTX helpers ----------------
__device__ __forceinline__ uint32_t smem_u32(const void* p) {
    uint32_t a;
    asm("{ .reg .u64 t; cvta.to.shared.u64 t, %1; cvt.u32.u64 %0, t; }" : "=r"(a) : "l"(p));
    return a;
}
__device__ __forceinline__ void cp16(uint32_t dst, const void* src) {
    asm volatile("cp.async.cg.shared.global [%0], [%1], 16;" ::"r"(dst), "l"(src) : "memory");
}
__device__ __forceinline__ void cp_commit() { asm volatile("cp.async.commit_group;" ::: "memory"); }
__device__ __forceinline__ void cp_wait2() { asm volatile("cp.async.wait_group 2;" ::: "memory"); }

__device__ __forceinline__ void ldsm4(uint32_t* r, uint32_t addr) {
    asm volatile("ldmatrix.sync.aligned.m8n8.x4.shared.b16 {%0,%1,%2,%3}, [%4];"
                 : "=r"(r[0]), "=r"(r[1]), "=r"(r[2]), "=r"(r[3])
                 : "r"(addr));
}
__device__ __forceinline__ void mma_bf16(float* c, const uint32_t* a, uint32_t b0, uint32_t b1) {
    asm volatile(
        "mma.sync.aligned.m16n8k16.row.col.f32.bf16.bf16.f32 "
        "{%0,%1,%2,%3}, {%4,%5,%6,%7}, {%8,%9}, {%0,%1,%2,%3};"
        : "+f"(c[0]), "+f"(c[1]), "+f"(c[2]), "+f"(c[3])
        : "r"(a[0]), "r"(a[1]), "r"(a[2]), "r"(a[3]), "r"(b0), "r"(b1));
}

// ---------------- split / fills / fold ----------------
__device__ __forceinline__ void split_bf16(float v, unsigned short& h, unsigned short& l) {
    __nv_bfloat16 bh = __float2bfloat16_rn(v);
    float fh = __bfloat162float(bh);
    __nv_bfloat16 bl = __float2bfloat16_rn(v - fh);
    h = __bfloat16_as_ushort(bh);
    l = __bfloat16_as_ushort(bl);
}
__device__ __forceinline__ uint2 pack_h(const unsigned short* h) {
    return make_uint2((uint32_t)h[0] | ((uint32_t)h[1] << 16),
                      (uint32_t)h[2] | ((uint32_t)h[3] << 16));
}

// Do[j][m] = cos(pi*(2j+1)(2m+1)/8192),  j,m < 2048
__global__ void fill_odd_kernel() {
    unsigned idx = blockIdx.x * blockDim.x + threadIdx.x;
    unsigned i4 = idx * 4;
    unsigned j = i4 >> 11;
    unsigned m0 = i4 & (MNH - 1);
    unsigned short h[4], l[4];
#pragma unroll
    for (int q = 0; q < 4; q++) {
        unsigned u = ((2u * j + 1u) * (2u * (m0 + q) + 1u)) & 16383u;
        split_bf16(cospif((float)u * (1.0f / 8192.0f)), h[q], l[q]);
    }
    ((uint2*)g_Dohi)[idx] = pack_h(h);
    ((uint2*)g_Dolo)[idx] = pack_h(l);
}

// Dee[j][m] = cos(pi*2j(2m+1)/4096), Deo[j][m] = cos(pi*(2j+1)(2m+1)/4096), j,m < 1024
__global__ void fill_even_kernel() {
    unsigned idx = blockIdx.x * blockDim.x + threadIdx.x;
    unsigned i4 = idx * 4;
    unsigned j = i4 >> 10;
    unsigned m0 = i4 & (MNQ - 1);
    unsigned short eh[4], el[4], oh[4], ol[4];
#pragma unroll
    for (int q = 0; q < 4; q++) {
        unsigned m2 = 2u * (m0 + q) + 1u;
        unsigned ue = (2u * j * m2) & 8191u;
        unsigned uo = ((2u * j + 1u) * m2) & 8191u;
        split_bf16(cospif((float)ue * (1.0f / 4096.0f)), eh[q], el[q]);
        split_bf16(cospif((float)uo * (1.0f / 4096.0f)), oh[q], ol[q]);
    }
    ((uint2*)g_Deehi)[idx] = pack_h(eh);
    ((uint2*)g_Deelo)[idx] = pack_h(el);
    ((uint2*)g_Deohi)[idx] = pack_h(oh);
    ((uint2*)g_Deolo)[idx] = pack_h(ol);
}

// Double fold of each 4096-wide row: d (2048), pp (1024), pm (1024), all split-bf16.
// which=0: src = xsrc;  which=1: src = g_T.  Dst buffers reused across passes.
__global__ void fold_split_kernel(const float* __restrict__ xsrc, int which) {
    unsigned idx = blockIdx.x * blockDim.x + threadIdx.x;  // MNF rows x 256 chunks
    unsigned row = idx >> 8;
    unsigned m0 = (idx & 255u) * 4u;  // 0..1020
    const float* s = (which ? (const float*)g_T : xsrc) + (size_t)row * MNF;

    float4 fa = *(const float4*)(s + m0);              // s[m]
    float4 fbr = *(const float4*)(s + (MNH - 4 - m0)); // rev -> s[2047-m]
    float4 fc = *(const float4*)(s + (MNH + m0));      // s[2048+m]
    float4 fdr = *(const float4*)(s + (MNF - 4 - m0)); // rev -> s[4095-m]
    float A[4] = {fa.x, fa.y, fa.z, fa.w};
    float B[4] = {fbr.w, fbr.z, fbr.y, fbr.x};
    float C[4] = {fc.x, fc.y, fc.z, fc.w};
    float D[4] = {fdr.w, fdr.z, fdr.y, fdr.x};

    unsigned short dfh[4], dfl[4], dbh[4], dbl[4], pph[4], ppl[4], pmh[4], pml[4];
#pragma unroll
    for (int q = 0; q < 4; q++) {
        split_bf16(A[q] - D[q], dfh[q], dfl[q]);  // d[m] = s[m]-s[4095-m]
        // d[2047-m] = s[2047-m]-s[2048+m]; store reversed (index 0 <-> q=3)
        split_bf16(B[3 - q] - C[3 - q], dbh[q], dbl[q]);
        float pf = A[q] + D[q];          // p[m]
        float pb = B[q] + C[q];          // p[2047-m]
        split_bf16(pf + pb, pph[q], ppl[q]);
        split_bf16(pf - pb, pmh[q], pml[q]);
    }
    size_t om = (size_t)row * MNH + m0;
    size_t omr = (size_t)row * MNH + (MNH - 4 - m0);
    size_t oq = (size_t)row * MNQ + m0;
    *(uint2*)(g_Bmhi + om) = pack_h(dfh);
    *(uint2*)(g_Bmlo + om) = pack_h(dfl);
    *(uint2*)(g_Bmhi + omr) = pack_h(dbh);
    *(uint2*)(g_Bmlo + omr) = pack_h(dbl);
    *(uint2*)(g_Bpphi + oq) = pack_h(pph);
    *(uint2*)(g_Bpplo + oq) = pack_h(ppl);
    *(uint2*)(g_Bpmhi + oq) = pack_h(pmh);
    *(uint2*)(g_Bpmlo + oq) = pack_h(pml);
}

// ---------------- GEMM ----------------
// One launch per pass, grid (32, 32):
//   blockIdx.y  0..15 : branch 0 (odd,  A=Do,  B=Bm,  K=2048, out row 2j+1)
//   blockIdx.y 16..23 : branch 1 (ee,   A=Dee, B=Bpp, K=1024, out row 4j)
//   blockIdx.y 24..31 : branch 2 (eo,   A=Deo, B=Bpm, K=1024, out row 4j+2)
// PASS 0: C = g_T;  PASS 1: C = outp.
template <int PASS>
__global__ void __launch_bounds__(256, 1) dct_gemm_kernel(float* __restrict__ outp) {
    extern __shared__ __align__(128) char smem[];
    const uint32_t sbase = smem_u32(smem);
    const int tid = threadIdx.x;
    const int lane = tid & 31;
    const int wid = tid >> 5;
    const int wm = wid & 1;
    const int wn = wid >> 1;
    const int ntile = blockIdx.x;
    const int yb = blockIdx.y;

    const int branch = (yb < 16) ? 0 : ((yb < 24) ? 1 : 2);
    const int mtile = yb - ((branch == 0) ? 0 : ((branch == 1) ? 16 : 24));
    const int kdim = (branch == 0) ? MNH : MNQ;
    const int nc = kdim >> 5;  // 64 or 32
    const int rowmul = (branch == 0) ? 2 : 4;
    const int rowadd = (branch == 0) ? 1 : ((branch == 1) ? 0 : 2);

    const unsigned short* __restrict__ Ah =
        (branch == 0) ? g_Dohi : ((branch == 1) ? g_Deehi : g_Deohi);
    const unsigned short* __restrict__ Al =
        (branch == 0) ? g_Dolo : ((branch == 1) ? g_Deelo : g_Deolo);
    const unsigned short* __restrict__ Bh =
        (branch == 0) ? g_Bmhi : ((branch == 1) ? g_Bpphi : g_Bpmhi);
    const unsigned short* __restrict__ Bl =
        (branch == 0) ? g_Bmlo : ((branch == 1) ? g_Bpplo : g_Bpmlo);
    float* __restrict__ C = (PASS == 0) ? g_T : outp;

    // ---- loader geometry: each thread moves 2 x 16B per operand tile ----
    const int row0 = tid >> 2;  // 0..63
    const int c0 = tid & 3;
    const uint32_t d0 = (uint32_t)row0 * ROWB + (uint32_t)c0 * 16;
    const uint32_t d1 = d0 + 64 * ROWB;
    const size_t aoff = (size_t)(mtile * BM + row0) * kdim + c0 * 8;
    const size_t boff = (size_t)(ntile * BN + row0) * kdim + c0 * 8;
    const size_t rstep = (size_t)64 * kdim;

    auto load_iter = [&](int it, int s) {
        const uint32_t sb = sbase + (uint32_t)s * STAGE_B;
        const size_t ko = (size_t)it * BK;
        cp16(sb + OFF_AH + d0, Ah + aoff + ko);
        cp16(sb + OFF_AH + d1, Ah + aoff + rstep + ko);
        cp16(sb + OFF_AL + d0, Al + aoff + ko);
        cp16(sb + OFF_AL + d1, Al + aoff + rstep + ko);
        cp16(sb + OFF_BH + d0, Bh + boff + ko);
        cp16(sb + OFF_BH + d1, Bh + boff + rstep + ko);
        cp16(sb + OFF_BL + d0, Bl + boff + ko);
        cp16(sb + OFF_BL + d1, Bl + boff + rstep + ko);
    };

    // ---- ldmatrix per-lane address offsets ----
    const int mt = lane >> 3;
    const uint32_t a_off = (uint32_t)(wm * 64 + (mt & 1) * 8 + (lane & 7)) * ROWB +
                           (uint32_t)((mt >> 1) * 16);
    const uint32_t b_off = (uint32_t)(wn * 32 + (mt >> 1) * 8 + (lane & 7)) * ROWB +
                           (uint32_t)((mt & 1) * 16);

    float acc[4][4][4];
#pragma unroll
    for (int i = 0; i < 4; i++)
#pragma unroll
        for (int j = 0; j < 4; j++)
#pragma unroll
            for (int q = 0; q < 4; q++) acc[i][j][q] = 0.0f;

    uint32_t ah[2][4][4], al[2][4][4], bh[2][2][4], bl[2][2][4];

    auto load_frags = [&](uint32_t sb, int buf, int ks) {
        const uint32_t ck = (uint32_t)ks * 32;
#pragma unroll
        for (int mi = 0; mi < 4; mi++) {
            ldsm4(ah[buf][mi], sb + OFF_AH + a_off + (uint32_t)mi * (16 * ROWB) + ck);
            ldsm4(al[buf][mi], sb + OFF_AL + a_off + (uint32_t)mi * (16 * ROWB) + ck);
        }
#pragma unroll
        for (int bp = 0; bp < 2; bp++) {
            ldsm4(bh[buf][bp], sb + OFF_BH + b_off + (uint32_t)bp * (16 * ROWB) + ck);
            ldsm4(bl[buf][bp], sb + OFF_BL + b_off + (uint32_t)bp * (16 * ROWB) + ck);
        }
    };
    auto mma_frags = [&](int buf) {
#pragma unroll
        for (int mi = 0; mi < 4; mi++)
#pragma unroll
            for (int ni = 0; ni < 4; ni++) {
                const int bp = ni >> 1, pr = (ni & 1) * 2;
                mma_bf16(acc[mi][ni], ah[buf][mi], bh[buf][bp][pr], bh[buf][bp][pr + 1]);
                mma_bf16(acc[mi][ni], ah[buf][mi], bl[buf][bp][pr], bl[buf][bp][pr + 1]);
                mma_bf16(acc[mi][ni], al[buf][mi], bh[buf][bp][pr], bh[buf][bp][pr + 1]);
            }
    };

    load_iter(0, 0);
    cp_commit();
    load_iter(1, 1);
    cp_commit();
    load_iter(2, 2);
    cp_commit();

    for (int it = 0; it < nc; ++it) {
        cp_wait2();
        __syncthreads();

        if (it + 3 < nc) load_iter(it + 3, (it + 3) & (STAGES - 1));
        cp_commit();

        const uint32_t sb = sbase + (uint32_t)(it & (STAGES - 1)) * STAGE_B;
        load_frags(sb, 0, 0);
        load_frags(sb, 1, 1);
        mma_frags(0);
        mma_frags(1);
    }

    // ---- epilogue: fp32, rows mapped per branch ----
    const int g = lane >> 2;
    const int cpair = (lane & 3) * 2;
#pragma unroll
    for (int mi = 0; mi < 4; mi++) {
#pragma unroll
        for (int ni = 0; ni < 4; ni++) {
            const int j0 = mtile * BM + wm * 64 + mi * 16 + g;
            const int j1 = j0 + 8;
            const int col = ntile * BN + wn * 32 + ni * 8 + cpair;
            *(float2*)(C + (size_t)(rowmul * j0 + rowadd) * MNF + col) =
                make_float2(acc[mi][ni][0], acc[mi][ni][1]);
            *(float2*)(C + (size_t)(rowmul * j1 + rowadd) * MNF + col) =
                make_float2(acc[mi][ni][2], acc[mi][ni][3]);
        }
    }
}

extern "C" void kernel_launch(void* const* d_in, const int* in_sizes, int n_in, void* d_out,
                              int out_size) {
    const float* x = (const float*)d_in[0];
    float* out = (float*)d_out;

    cudaFuncSetAttribute(dct_gemm_kernel<0>, cudaFuncAttributeMaxDynamicSharedMemorySize, SMEM_SZ);
    cudaFuncSetAttribute(dct_gemm_kernel<1>, cudaFuncAttributeMaxDynamicSharedMemorySize, SMEM_SZ);

    fill_odd_kernel<<<(MNH * MNH / 4) / 256, 256>>>();
    fill_even_kernel<<<(MNQ * MNQ / 4) / 256, 256>>>();

    fold_split_kernel<<<MNF, 256>>>(x, 0);

    dim3 grid(MNF / BN, 32);  // (32, 32): y<16 odd, 16..23 ee, 24..31 eo
    dct_gemm_kernel<0><<<grid, 256, SMEM_SZ>>>(nullptr);  // -> g_T

    fold_split_kernel<<<MNF, 256>>>(nullptr, 1);  // fold T into same B buffers

    dct_gemm_kernel<1><<<grid, 256, SMEM_SZ>>>(out);
}